// round 2
// baseline (speedup 1.0000x reference)
#include <cuda_runtime.h>
#include <math.h>

#define Dm 1024
#define Hh 16
#define DHd 64
#define Bb 4
#define Ss 2048
#define NROWS (Bb*Ss)   // 8192
#define APAD 68         // float4-aligned padded row stride (68*4B = 272B, 16B aligned)

// ---- scratch (static device allocations; no cudaMalloc allowed) ----
__device__ float g_mu[3*NROWS];
__device__ float g_rs[3*NROWS];
__device__ float g_q[NROWS*Dm];   // [B,H,S,dh]
__device__ float g_k[NROWS*Dm];   // [B,H,S,dh]
__device__ float g_v[NROWS*Dm];   // [B,H,S,dh]
__device__ float g_ao[NROWS*Dm];  // attention output, [B,H,S,dh]

// ============================================================
// 1) per-row layernorm stats for Q, K, V  (3*8192 rows of 1024)
// ============================================================
__global__ void ln_stats_kernel(const float* __restrict__ Q,
                                const float* __restrict__ K,
                                const float* __restrict__ V) {
    int row = blockIdx.x;              // 0 .. 3*8192-1
    int which = row >> 13;             // /8192
    int r = row & (NROWS - 1);
    const float* x = (which == 0 ? Q : (which == 1 ? K : V)) + (size_t)r * Dm;

    float s = 0.f, s2 = 0.f;
    for (int i = threadIdx.x; i < Dm; i += 256) {
        float v = x[i];
        s += v; s2 += v * v;
    }
    #pragma unroll
    for (int o = 16; o > 0; o >>= 1) {
        s  += __shfl_xor_sync(0xffffffffu, s,  o);
        s2 += __shfl_xor_sync(0xffffffffu, s2, o);
    }
    __shared__ float sh[16];
    int w = threadIdx.x >> 5;
    if ((threadIdx.x & 31) == 0) { sh[w] = s; sh[w + 8] = s2; }
    __syncthreads();
    if (threadIdx.x == 0) {
        float ts = 0.f, ts2 = 0.f;
        #pragma unroll
        for (int i = 0; i < 8; i++) { ts += sh[i]; ts2 += sh[i + 8]; }
        float mu  = ts / (float)Dm;
        float var = ts2 / (float)Dm - mu * mu;
        g_mu[row] = mu;
        g_rs[row] = rsqrtf(var + 1e-6f);
    }
}

// ============================================================
// 2) GEMM with LN fused on A-load:  out = LN(X) @ W + b
//    epilogue scatters into [B,H,S,dh] layout
//    block: 256 threads, tile 64x64, BK=16, 4x4 micro-tile
// ============================================================
__global__ void gemm_ln_kernel(const float* __restrict__ X,
                               const float* __restrict__ W,
                               const float* __restrict__ bias,
                               const float* __restrict__ gamma,
                               const float* __restrict__ beta,
                               const float* __restrict__ mu,
                               const float* __restrict__ rs,
                               float* __restrict__ out) {
    __shared__ float As[16 * 65];   // [k][m] transposed, padded (scalar access only)
    __shared__ float Bs[16 * 64];   // [k][n] (vector access, stride 64 aligned)

    int tid = threadIdx.x;
    int tx = tid & 15, ty = tid >> 4;
    int m0 = blockIdx.y * 64, n0 = blockIdx.x * 64;

    float acc[4][4] = {};

    for (int kb = 0; kb < Dm; kb += 16) {
        #pragma unroll
        for (int l = 0; l < 4; l++) {
            int e  = tid + l * 256;          // 1024 elems
            int kr = e & 15, ar = e >> 4;
            int r  = m0 + ar, kg = kb + kr;
            float v = X[(size_t)r * Dm + kg];
            v = (v - mu[r]) * rs[r] * gamma[kg] + beta[kg];
            As[kr * 65 + ar] = v;
        }
        #pragma unroll
        for (int l = 0; l < 4; l++) {
            int e  = tid + l * 256;
            int nc = e & 63, kr = e >> 6;
            Bs[kr * 64 + nc] = W[(size_t)(kb + kr) * Dm + n0 + nc];
        }
        __syncthreads();
        #pragma unroll
        for (int kk = 0; kk < 16; kk++) {
            float ar[4];
            #pragma unroll
            for (int i = 0; i < 4; i++) ar[i] = As[kk * 65 + ty * 4 + i];
            float4 b4 = *(const float4*)&Bs[kk * 64 + tx * 4];
            float br[4] = {b4.x, b4.y, b4.z, b4.w};
            #pragma unroll
            for (int i = 0; i < 4; i++)
                #pragma unroll
                for (int j = 0; j < 4; j++)
                    acc[i][j] += ar[i] * br[j];
        }
        __syncthreads();
    }

    #pragma unroll
    for (int i = 0; i < 4; i++) {
        int r = m0 + ty * 4 + i;
        int b = r >> 11;            // /2048
        int s = r & 2047;
        #pragma unroll
        for (int j = 0; j < 4; j++) {
            int c  = n0 + tx * 4 + j;
            int h  = c >> 6;
            int dd = c & 63;
            out[(((size_t)(b * Hh + h) * Ss + s) << 6) + dd] = acc[i][j] + bias[c];
        }
    }
}

// ============================================================
// 3) causal attention (flash-style online softmax), fp32
//    grid: (S/64, B*H); block 256 threads; 64-row q tile
//    all float4-accessed tiles use APAD=68 stride (16B aligned)
// ============================================================
__global__ void attn_kernel(float* __restrict__ out) {
    extern __shared__ float sm[];
    float* Qs  = sm;                   // [row][d]   64xAPAD
    float* KsT = sm + 64 * APAD;       // [d][key]   64xAPAD
    float* Vs  = KsT + 64 * APAD;      // [key][d]   64xAPAD
    float* Ps  = Vs + 64 * APAD;       // [row][key] 64xAPAD

    int bh = blockIdx.y;             // b*16+h
    int mt = blockIdx.x;
    int tid = threadIdx.x;
    int tx = tid & 15, ty = tid >> 4;

    const float* qb = g_q + (size_t)bh * Ss * DHd;
    const float* kb = g_k + (size_t)bh * Ss * DHd;
    const float* vb = g_v + (size_t)bh * Ss * DHd;

    int q0 = mt * 64;

    #pragma unroll
    for (int l = 0; l < 16; l++) {
        int e = tid + l * 256;       // 4096 elems
        int d = e & 63, r = e >> 6;
        Qs[r * APAD + d] = qb[(size_t)(q0 + r) * DHd + d];
    }

    float m[4], lsum[4], acc[4][4] = {};
    #pragma unroll
    for (int i = 0; i < 4; i++) { m[i] = -1e30f; lsum[i] = 0.f; }

    int kend = q0 + 64;
    for (int kt = 0; kt < kend; kt += 64) {
        __syncthreads();             // protect smem from previous iter's readers
        #pragma unroll
        for (int l = 0; l < 16; l++) {
            int e = tid + l * 256;
            int d = e & 63, r = e >> 6;
            float kv = kb[(size_t)(kt + r) * DHd + d];
            KsT[d * APAD + r] = kv;
            Vs[r * APAD + d]  = vb[(size_t)(kt + r) * DHd + d];
        }
        __syncthreads();

        float sc[4][4] = {};
        #pragma unroll 8
        for (int d = 0; d < 64; d++) {
            float4 k4 = *(const float4*)&KsT[d * APAD + tx * 4];
            float kr[4] = {k4.x, k4.y, k4.z, k4.w};
            #pragma unroll
            for (int i = 0; i < 4; i++) {
                float qv = Qs[(ty * 4 + i) * APAD + d];
                #pragma unroll
                for (int j = 0; j < 4; j++) sc[i][j] += qv * kr[j];
            }
        }

        if (kt == q0) {              // only the diagonal tile needs masking
            #pragma unroll
            for (int i = 0; i < 4; i++) {
                int qi = q0 + ty * 4 + i;
                #pragma unroll
                for (int j = 0; j < 4; j++) {
                    int kidx = kt + tx * 4 + j;
                    if (kidx > qi) sc[i][j] = -1e30f;
                }
            }
        }

        #pragma unroll
        for (int i = 0; i < 4; i++) {
            float tmax = fmaxf(fmaxf(sc[i][0], sc[i][1]), fmaxf(sc[i][2], sc[i][3]));
            #pragma unroll
            for (int o = 8; o > 0; o >>= 1)
                tmax = fmaxf(tmax, __shfl_xor_sync(0xffffffffu, tmax, o));
            float mn   = fmaxf(m[i], tmax);
            float corr = __expf(m[i] - mn);
            m[i] = mn;

            float p0 = __expf(sc[i][0] - mn);
            float p1 = __expf(sc[i][1] - mn);
            float p2 = __expf(sc[i][2] - mn);
            float p3 = __expf(sc[i][3] - mn);
            float ls = p0 + p1 + p2 + p3;
            #pragma unroll
            for (int o = 8; o > 0; o >>= 1)
                ls += __shfl_xor_sync(0xffffffffu, ls, o);
            lsum[i] = lsum[i] * corr + ls;
            #pragma unroll
            for (int j = 0; j < 4; j++) acc[i][j] *= corr;
            *(float4*)&Ps[(ty * 4 + i) * APAD + tx * 4] = make_float4(p0, p1, p2, p3);
        }
        __syncthreads();

        #pragma unroll 8
        for (int k = 0; k < 64; k++) {
            float4 v4 = *(const float4*)&Vs[k * APAD + tx * 4];
            #pragma unroll
            for (int i = 0; i < 4; i++) {
                float pv = Ps[(ty * 4 + i) * APAD + k];
                acc[i][0] += pv * v4.x;
                acc[i][1] += pv * v4.y;
                acc[i][2] += pv * v4.z;
                acc[i][3] += pv * v4.w;
            }
        }
    }

    float* ob = out + (size_t)bh * Ss * DHd;
    #pragma unroll
    for (int i = 0; i < 4; i++) {
        int r = q0 + ty * 4 + i;
        float inv = 1.f / lsum[i];
        #pragma unroll
        for (int j = 0; j < 4; j++)
            ob[(size_t)r * DHd + tx * 4 + j] = acc[i][j] * inv;
    }
}

// ============================================================
// 4) output projection + bias + residual:
//    out[r][c] = (AO @ Wo)[r][c] + bo[c] + Q[r][c]
//    AO is read from [B,H,S,dh] layout
// ============================================================
__global__ void gemm_out_kernel(const float* __restrict__ AO,
                                const float* __restrict__ W,
                                const float* __restrict__ bias,
                                const float* __restrict__ Qin,
                                float* __restrict__ out) {
    __shared__ float As[16 * 65];
    __shared__ float Bs[16 * 64];

    int tid = threadIdx.x;
    int tx = tid & 15, ty = tid >> 4;
    int m0 = blockIdx.y * 64, n0 = blockIdx.x * 64;

    float acc[4][4] = {};

    for (int kb = 0; kb < Dm; kb += 16) {
        #pragma unroll
        for (int l = 0; l < 4; l++) {
            int e  = tid + l * 256;
            int kr = e & 15, ar = e >> 4;
            int r  = m0 + ar, kg = kb + kr;
            int b  = r >> 11, s = r & 2047;
            int h  = kg >> 6, dd = kg & 63;
            As[kr * 65 + ar] = AO[(((size_t)(b * Hh + h) * Ss + s) << 6) + dd];
        }
        #pragma unroll
        for (int l = 0; l < 4; l++) {
            int e  = tid + l * 256;
            int nc = e & 63, kr = e >> 6;
            Bs[kr * 64 + nc] = W[(size_t)(kb + kr) * Dm + n0 + nc];
        }
        __syncthreads();
        #pragma unroll
        for (int kk = 0; kk < 16; kk++) {
            float ar[4];
            #pragma unroll
            for (int i = 0; i < 4; i++) ar[i] = As[kk * 65 + ty * 4 + i];
            float4 b4 = *(const float4*)&Bs[kk * 64 + tx * 4];
            float br[4] = {b4.x, b4.y, b4.z, b4.w};
            #pragma unroll
            for (int i = 0; i < 4; i++)
                #pragma unroll
                for (int j = 0; j < 4; j++)
                    acc[i][j] += ar[i] * br[j];
        }
        __syncthreads();
    }

    #pragma unroll
    for (int i = 0; i < 4; i++) {
        int r = m0 + ty * 4 + i;
        #pragma unroll
        for (int j = 0; j < 4; j++) {
            int c = n0 + tx * 4 + j;
            out[(size_t)r * Dm + c] = acc[i][j] + bias[c] + Qin[(size_t)r * Dm + c];
        }
    }
}

// ============================================================
// launch
// ============================================================
extern "C" void kernel_launch(void* const* d_in, const int* in_sizes, int n_in,
                              void* d_out, int out_size) {
    const float* Q     = (const float*)d_in[0];
    const float* K     = (const float*)d_in[1];
    const float* V     = (const float*)d_in[2];
    const float* Wq    = (const float*)d_in[3];
    const float* bq    = (const float*)d_in[4];
    const float* Wk    = (const float*)d_in[5];
    const float* bk    = (const float*)d_in[6];
    const float* Wv    = (const float*)d_in[7];
    const float* bv    = (const float*)d_in[8];
    const float* Wo    = (const float*)d_in[9];
    const float* bo    = (const float*)d_in[10];
    const float* gamma = (const float*)d_in[11];
    const float* beta  = (const float*)d_in[12];
    float* out = (float*)d_out;

    float *mu_p, *rs_p, *q_p, *k_p, *v_p, *ao_p;
    cudaGetSymbolAddress((void**)&mu_p, g_mu);
    cudaGetSymbolAddress((void**)&rs_p, g_rs);
    cudaGetSymbolAddress((void**)&q_p,  g_q);
    cudaGetSymbolAddress((void**)&k_p,  g_k);
    cudaGetSymbolAddress((void**)&v_p,  g_v);
    cudaGetSymbolAddress((void**)&ao_p, g_ao);

    // 1) LN stats
    ln_stats_kernel<<<3 * NROWS, 256>>>(Q, K, V);

    // 2) projections
    dim3 ggrid(Dm / 64, NROWS / 64);   // (16, 128)
    gemm_ln_kernel<<<ggrid, 256>>>(Q, Wq, bq, gamma, beta, mu_p,             rs_p,             q_p);
    gemm_ln_kernel<<<ggrid, 256>>>(K, Wk, bk, gamma, beta, mu_p + NROWS,     rs_p + NROWS,     k_p);
    gemm_ln_kernel<<<ggrid, 256>>>(V, Wv, bv, gamma, beta, mu_p + 2 * NROWS, rs_p + 2 * NROWS, v_p);

    // 3) attention
    size_t smem = 4 * 64 * APAD * sizeof(float);   // 69632 B
    cudaFuncSetAttribute(attn_kernel, cudaFuncAttributeMaxDynamicSharedMemorySize, (int)smem);
    attn_kernel<<<dim3(Ss / 64, Bb * Hh), 256, smem>>>(ao_p);

    // 4) output projection + residual
    gemm_out_kernel<<<ggrid, 256>>>(ao_p, Wo, bo, Q, out);
}

// round 4
// speedup vs baseline: 1.4611x; 1.4611x over previous
#include <cuda_runtime.h>
#include <cuda_bf16.h>
#include <cstdint>
#include <math.h>

#define Dm 1024
#define Hh 16
#define DHd 64
#define Bb 4
#define Ss 2048
#define NROWS (Bb*Ss)   // 8192
#define APAD 68

// ---------------- static device scratch ----------------
__device__ float g_mu[3*NROWS];
__device__ float g_rs[3*NROWS];
// bf16 hi/lo splits of raw inputs
__device__ __nv_bfloat16 g_xh_q[NROWS*Dm]; __device__ __nv_bfloat16 g_xl_q[NROWS*Dm];
__device__ __nv_bfloat16 g_xh_k[NROWS*Dm]; __device__ __nv_bfloat16 g_xl_k[NROWS*Dm];
__device__ __nv_bfloat16 g_xh_v[NROWS*Dm]; __device__ __nv_bfloat16 g_xl_v[NROWS*Dm];
// transposed, gamma-scaled, bf16-split weights: [4][N=1024][K=1024]
__device__ __nv_bfloat16 g_wh[4*Dm*Dm];
__device__ __nv_bfloat16 g_wl[4*Dm*Dm];
__device__ float g_c1[3*Dm];
__device__ float g_c2[3*Dm];
// projected q,k,v in [B,H,S,dh], fp32
__device__ float g_q[NROWS*Dm];
__device__ float g_k[NROWS*Dm];
__device__ float g_v[NROWS*Dm];
// attention output, row-major, bf16 pre-split
__device__ __nv_bfloat16 g_aoh[NROWS*Dm];
__device__ __nv_bfloat16 g_aol[NROWS*Dm];

// ---------------- helpers ----------------
__device__ __forceinline__ uint32_t smem_u32(const void* p) {
    uint32_t a;
    asm("{ .reg .u64 t; cvta.to.shared.u64 t, %1; cvt.u32.u64 %0, t; }" : "=r"(a) : "l"(p));
    return a;
}
__device__ __forceinline__ void cp16(uint32_t s, const void* g) {
    asm volatile("cp.async.cg.shared.global [%0], [%1], 16;\n" :: "r"(s), "l"(g));
}
__device__ __forceinline__ void ldmA(uint32_t addr, uint32_t& r0, uint32_t& r1,
                                     uint32_t& r2, uint32_t& r3) {
    asm volatile("ldmatrix.sync.aligned.m8n8.x4.shared.b16 {%0,%1,%2,%3}, [%4];"
                 : "=r"(r0), "=r"(r1), "=r"(r2), "=r"(r3) : "r"(addr));
}
__device__ __forceinline__ void mma16816(float* c, uint32_t a0, uint32_t a1,
                                         uint32_t a2, uint32_t a3,
                                         uint32_t b0, uint32_t b1) {
    asm volatile("mma.sync.aligned.m16n8k16.row.col.f32.bf16.bf16.f32 "
                 "{%0,%1,%2,%3}, {%4,%5,%6,%7}, {%8,%9}, {%0,%1,%2,%3};"
                 : "+f"(c[0]), "+f"(c[1]), "+f"(c[2]), "+f"(c[3])
                 : "r"(a0), "r"(a1), "r"(a2), "r"(a3), "r"(b0), "r"(b1));
}
__device__ __forceinline__ uint32_t packbf2(float a, float b) {
    __nv_bfloat162 t;
    t.x = __float2bfloat16(a);
    t.y = __float2bfloat16(b);
    return *(uint32_t*)&t;
}

// ============================================================
// 1) LN stats + bf16 hi/lo split of raw inputs (fused)
// ============================================================
__global__ void ln_split_kernel(const float* __restrict__ Q,
                                const float* __restrict__ K,
                                const float* __restrict__ V) {
    int row = blockIdx.x;
    int which = row >> 13;
    int r = row & (NROWS - 1);
    const float* x; __nv_bfloat16* xh; __nv_bfloat16* xl;
    if (which == 0)      { x = Q; xh = g_xh_q; xl = g_xl_q; }
    else if (which == 1) { x = K; xh = g_xh_k; xl = g_xl_k; }
    else                 { x = V; xh = g_xh_v; xl = g_xl_v; }
    size_t base = (size_t)r * Dm;

    float v[4];
    float s = 0.f, s2 = 0.f;
    #pragma unroll
    for (int l = 0; l < 4; l++) {
        v[l] = x[base + threadIdx.x + l * 256];
        s += v[l]; s2 += v[l] * v[l];
    }
    #pragma unroll
    for (int o = 16; o > 0; o >>= 1) {
        s  += __shfl_xor_sync(0xffffffffu, s,  o);
        s2 += __shfl_xor_sync(0xffffffffu, s2, o);
    }
    __shared__ float sh[16];
    int w = threadIdx.x >> 5;
    if ((threadIdx.x & 31) == 0) { sh[w] = s; sh[w + 8] = s2; }
    __syncthreads();
    if (threadIdx.x == 0) {
        float ts = 0.f, ts2 = 0.f;
        #pragma unroll
        for (int i = 0; i < 8; i++) { ts += sh[i]; ts2 += sh[i + 8]; }
        float muv = ts / (float)Dm;
        float var = ts2 / (float)Dm - muv * muv;
        g_mu[row] = muv;
        g_rs[row] = rsqrtf(var + 1e-6f);
    }
    #pragma unroll
    for (int l = 0; l < 4; l++) {
        __nv_bfloat16 h = __float2bfloat16(v[l]);
        xh[base + threadIdx.x + l * 256] = h;
        xl[base + threadIdx.x + l * 256] = __float2bfloat16(v[l] - __bfloat162float(h));
    }
}

// ============================================================
// 2a) weight prep: transpose to [N][K], gamma-scale, bf16 split
// ============================================================
__global__ void wprep_kernel(const float* __restrict__ Wq, const float* __restrict__ Wk,
                             const float* __restrict__ Wv, const float* __restrict__ Wo,
                             const float* __restrict__ gamma) {
    int w = blockIdx.z;
    const float* W = (w == 0) ? Wq : (w == 1) ? Wk : (w == 2) ? Wv : Wo;
    __shared__ float ts[64][65];
    int n0 = blockIdx.x * 64, k0 = blockIdx.y * 64;
    int tx = threadIdx.x & 63, ty = threadIdx.x >> 6;
    #pragma unroll
    for (int l = 0; l < 16; l++) {
        int k = ty + l * 4;
        float g = (w < 3) ? gamma[k0 + k] : 1.f;
        ts[k][tx] = g * W[(size_t)(k0 + k) * Dm + n0 + tx];
    }
    __syncthreads();
    __nv_bfloat16* whp = g_wh + (size_t)w * Dm * Dm;
    __nv_bfloat16* wlp = g_wl + (size_t)w * Dm * Dm;
    #pragma unroll
    for (int l = 0; l < 16; l++) {
        int n = ty + l * 4;
        float val = ts[tx][n];
        __nv_bfloat16 h = __float2bfloat16(val);
        size_t o = (size_t)(n0 + n) * Dm + k0 + tx;
        whp[o] = h;
        wlp[o] = __float2bfloat16(val - __bfloat162float(h));
    }
}

// 2b) column constants
__global__ void wcols_kernel(const float* __restrict__ Wq, const float* __restrict__ Wk,
                             const float* __restrict__ Wv,
                             const float* __restrict__ gamma, const float* __restrict__ beta,
                             const float* __restrict__ bq, const float* __restrict__ bk,
                             const float* __restrict__ bv) {
    int w = blockIdx.y;
    int n = blockIdx.x * 256 + threadIdx.x;
    const float* W = (w == 0) ? Wq : (w == 1) ? Wk : Wv;
    const float* b = (w == 0) ? bq : (w == 1) ? bk : bv;
    float a1 = 0.f, a2 = 0.f;
    for (int k = 0; k < Dm; k++) {
        float wv = W[(size_t)k * Dm + n];
        a1 += gamma[k] * wv;
        a2 += beta[k] * wv;
    }
    g_c1[w * Dm + n] = a1;
    g_c2[w * Dm + n] = a2 + b[n];
}

// ============================================================
// 3) bf16 mma.sync GEMM, 3-pass split (hh + hl + lh), fp32 acc.
//    tile 128x128x32, 8 warps (2M x 4N), warp tile 64x32,
//    3-stage cp.async, XOR-swizzled smem, ldmatrix A / LDS.32 B.
//    MODE 0: LN epilogue + scatter to [B,H,S,dh]
//    MODE 1: +bias +residual, row-major out
// ============================================================
#define BM 128
#define BN 128
#define BK 32
#define KBYTES 64            // BK * 2 bytes
#define STG_A 8192
#define STG   16384          // A + B per stage
#define NSTG  3
#define NT    96             // 3 passes * 32 k-blocks

template<int MODE>
__global__ void __launch_bounds__(256, 1) gemm_mma_kernel(
    const __nv_bfloat16* __restrict__ Ah, const __nv_bfloat16* __restrict__ Al,
    const __nv_bfloat16* __restrict__ Bh, const __nv_bfloat16* __restrict__ Bl,
    const float* __restrict__ c1, const float* __restrict__ c2,
    const float* __restrict__ rs, const float* __restrict__ mu,
    const float* __restrict__ resid,
    float* __restrict__ out)
{
    extern __shared__ char smem[];
    uint32_t sbase = smem_u32(smem);
    int tid = threadIdx.x, lane = tid & 31, wid = tid >> 5;
    int warpM = wid & 1, warpN = wid >> 1;
    int m0 = blockIdx.y * BM, n0 = blockIdx.x * BN;

    float acc[4][4][4] = {};   // [mf][nf][reg]

    auto prefetch = [&](int t) {
        int s = t % NSTG;
        int pass = t >> 5, kb = (t & 31) * BK;
        const __nv_bfloat16* Ap = (pass == 2) ? Al : Ah;
        const __nv_bfloat16* Bp = (pass == 1) ? Bl : Bh;
        uint32_t sa = sbase + s * STG, sb = sa + STG_A;
        #pragma unroll
        for (int l = 0; l < 2; l++) {
            int e = tid + l * 256;          // 512 16B-chunks each side
            int m = e >> 2, kc = e & 3;
            uint32_t sw = m * KBYTES + ((kc ^ (m & 3)) << 4);
            cp16(sa + sw, Ap + (size_t)(m0 + m) * Dm + kb + kc * 8);
            cp16(sb + sw, Bp + (size_t)(n0 + m) * Dm + kb + kc * 8);
        }
    };

    prefetch(0); asm volatile("cp.async.commit_group;\n" ::: "memory");
    prefetch(1); asm volatile("cp.async.commit_group;\n" ::: "memory");

    for (int t = 0; t < NT; t++) {
        asm volatile("cp.async.wait_group 1;\n" ::: "memory");
        __syncthreads();
        int s = t % NSTG;
        uint32_t sa = sbase + s * STG, sb = sa + STG_A;
        #pragma unroll
        for (int ks = 0; ks < 2; ks++) {
            uint32_t afr[4][4];
            #pragma unroll
            for (int mf = 0; mf < 4; mf++) {
                int row = warpM * 64 + mf * 16 + (lane & 15);
                int chunk = ks * 2 + (lane >> 4);
                uint32_t addr = sa + row * KBYTES + ((chunk ^ (row & 3)) << 4);
                ldmA(addr, afr[mf][0], afr[mf][1], afr[mf][2], afr[mf][3]);
            }
            #pragma unroll
            for (int nf = 0; nf < 4; nf++) {
                int n = warpN * 32 + nf * 8 + (lane >> 2);
                int kb0 = ks * 32 + (lane & 3) * 4;     // byte offset of b0
                int c0 = kb0 >> 4, o0 = kb0 & 15;
                uint32_t ab0 = sb + n * KBYTES + (((c0 ^ (n & 3)) << 4) | o0);
                uint32_t ab1 = sb + n * KBYTES + ((((c0 + 1) ^ (n & 3)) << 4) | o0);
                uint32_t b0, b1;
                asm volatile("ld.shared.b32 %0, [%1];" : "=r"(b0) : "r"(ab0));
                asm volatile("ld.shared.b32 %0, [%1];" : "=r"(b1) : "r"(ab1));
                #pragma unroll
                for (int mf = 0; mf < 4; mf++)
                    mma16816(acc[mf][nf], afr[mf][0], afr[mf][1], afr[mf][2], afr[mf][3],
                             b0, b1);
            }
        }
        __syncthreads();
        if (t + 2 < NT) prefetch(t + 2);
        asm volatile("cp.async.commit_group;\n" ::: "memory");
    }

    // ---- epilogue ----
    int groupID = lane >> 2, tg = lane & 3;
    #pragma unroll
    for (int mf = 0; mf < 4; mf++) {
        #pragma unroll
        for (int half = 0; half < 2; half++) {
            int r = m0 + warpM * 64 + mf * 16 + groupID + half * 8;
            float rsv = 1.f, muv = 0.f;
            if (MODE == 0) { rsv = rs[r]; muv = mu[r]; }
            int b = r >> 11, srow = r & 2047;
            #pragma unroll
            for (int nf = 0; nf < 4; nf++) {
                int c = n0 + warpN * 32 + nf * 8 + 2 * tg;
                float x0 = acc[mf][nf][2 * half + 0];
                float x1 = acc[mf][nf][2 * half + 1];
                if (MODE == 0) {
                    float2 c1v = *(const float2*)(c1 + c);
                    float2 c2v = *(const float2*)(c2 + c);
                    float2 o;
                    o.x = rsv * (x0 - muv * c1v.x) + c2v.x;
                    o.y = rsv * (x1 - muv * c1v.y) + c2v.y;
                    int h = c >> 6, dd = c & 63;
                    *(float2*)(out + (((size_t)(b * Hh + h) * Ss + srow) << 6) + dd) = o;
                } else {
                    float2 bo2 = *(const float2*)(c2 + c);
                    float2 q2  = *(const float2*)(resid + (size_t)r * Dm + c);
                    float2 o;
                    o.x = x0 + bo2.x + q2.x;
                    o.y = x1 + bo2.y + q2.y;
                    *(float2*)(out + (size_t)r * Dm + c) = o;
                }
            }
        }
    }
}

// ============================================================
// 4) causal attention (flash-style, fp32 SIMT) — bf16-split output
// ============================================================
__global__ void attn_kernel(__nv_bfloat16* __restrict__ outh,
                            __nv_bfloat16* __restrict__ outl) {
    extern __shared__ float sm[];
    float* Qs  = sm;
    float* KsT = sm + 64 * APAD;
    float* Vs  = KsT + 64 * APAD;
    float* Ps  = Vs + 64 * APAD;

    int bh = blockIdx.y;
    int mt = blockIdx.x;
    int tid = threadIdx.x;
    int tx = tid & 15, ty = tid >> 4;

    const float* qb = g_q + (size_t)bh * Ss * DHd;
    const float* kb = g_k + (size_t)bh * Ss * DHd;
    const float* vb = g_v + (size_t)bh * Ss * DHd;

    int q0 = mt * 64;

    #pragma unroll
    for (int l = 0; l < 16; l++) {
        int e = tid + l * 256;
        int d = e & 63, r = e >> 6;
        Qs[r * APAD + d] = qb[(size_t)(q0 + r) * DHd + d];
    }

    float m[4], lsum[4], acc[4][4] = {};
    #pragma unroll
    for (int i = 0; i < 4; i++) { m[i] = -1e30f; lsum[i] = 0.f; }

    int kend = q0 + 64;
    for (int kt = 0; kt < kend; kt += 64) {
        __syncthreads();
        #pragma unroll
        for (int l = 0; l < 16; l++) {
            int e = tid + l * 256;
            int d = e & 63, r = e >> 6;
            KsT[d * APAD + r] = kb[(size_t)(kt + r) * DHd + d];
            Vs[r * APAD + d]  = vb[(size_t)(kt + r) * DHd + d];
        }
        __syncthreads();

        float sc[4][4] = {};
        #pragma unroll 8
        for (int d = 0; d < 64; d++) {
            float4 k4 = *(const float4*)&KsT[d * APAD + tx * 4];
            float kr[4] = {k4.x, k4.y, k4.z, k4.w};
            #pragma unroll
            for (int i = 0; i < 4; i++) {
                float qv = Qs[(ty * 4 + i) * APAD + d];
                #pragma unroll
                for (int j = 0; j < 4; j++) sc[i][j] += qv * kr[j];
            }
        }

        if (kt == q0) {
            #pragma unroll
            for (int i = 0; i < 4; i++) {
                int qi = q0 + ty * 4 + i;
                #pragma unroll
                for (int j = 0; j < 4; j++) {
                    int kidx = kt + tx * 4 + j;
                    if (kidx > qi) sc[i][j] = -1e30f;
                }
            }
        }

        #pragma unroll
        for (int i = 0; i < 4; i++) {
            float tmax = fmaxf(fmaxf(sc[i][0], sc[i][1]), fmaxf(sc[i][2], sc[i][3]));
            #pragma unroll
            for (int o = 8; o > 0; o >>= 1)
                tmax = fmaxf(tmax, __shfl_xor_sync(0xffffffffu, tmax, o));
            float mn = fmaxf(m[i], tmax);
            float corr = __expf(m[i] - mn);
            m[i] = mn;
            float p0 = __expf(sc[i][0] - mn);
            float p1 = __expf(sc[i][1] - mn);
            float p2 = __expf(sc[i][2] - mn);
            float p3 = __expf(sc[i][3] - mn);
            float ls = p0 + p1 + p2 + p3;
            #pragma unroll
            for (int o = 8; o > 0; o >>= 1)
                ls += __shfl_xor_sync(0xffffffffu, ls, o);
            lsum[i] = lsum[i] * corr + ls;
            #pragma unroll
            for (int j = 0; j < 4; j++) acc[i][j] *= corr;
            *(float4*)&Ps[(ty * 4 + i) * APAD + tx * 4] = make_float4(p0, p1, p2, p3);
        }
        __syncthreads();

        #pragma unroll 8
        for (int k = 0; k < 64; k++) {
            float4 v4 = *(const float4*)&Vs[k * APAD + tx * 4];
            #pragma unroll
            for (int i = 0; i < 4; i++) {
                float pv = Ps[(ty * 4 + i) * APAD + k];
                acc[i][0] += pv * v4.x;
                acc[i][1] += pv * v4.y;
                acc[i][2] += pv * v4.z;
                acc[i][3] += pv * v4.w;
            }
        }
    }

    int b = bh >> 4, h = bh & 15;
    #pragma unroll
    for (int i = 0; i < 4; i++) {
        int r = q0 + ty * 4 + i;
        float inv = 1.f / lsum[i];
        size_t addr = ((size_t)(b * Ss + r)) * Dm + h * 64 + tx * 4;
        float v0 = acc[i][0] * inv, v1 = acc[i][1] * inv;
        float v2 = acc[i][2] * inv, v3 = acc[i][3] * inv;
        __nv_bfloat16 h0 = __float2bfloat16(v0), h1 = __float2bfloat16(v1);
        __nv_bfloat16 h2 = __float2bfloat16(v2), h3 = __float2bfloat16(v3);
        uint2 hv, lv;
        hv.x = packbf2(v0, v1); hv.y = packbf2(v2, v3);
        // recompute hv packing exactly from the h values to keep hi/lo consistent
        {
            __nv_bfloat162 t01, t23;
            t01.x = h0; t01.y = h1; t23.x = h2; t23.y = h3;
            hv.x = *(uint32_t*)&t01; hv.y = *(uint32_t*)&t23;
        }
        lv.x = packbf2(v0 - __bfloat162float(h0), v1 - __bfloat162float(h1));
        lv.y = packbf2(v2 - __bfloat162float(h2), v3 - __bfloat162float(h3));
        *(uint2*)(outh + addr) = hv;
        *(uint2*)(outl + addr) = lv;
    }
}

// ============================================================
// launch
// ============================================================
extern "C" void kernel_launch(void* const* d_in, const int* in_sizes, int n_in,
                              void* d_out, int out_size) {
    const float* Q     = (const float*)d_in[0];
    const float* K     = (const float*)d_in[1];
    const float* V     = (const float*)d_in[2];
    const float* Wq    = (const float*)d_in[3];
    const float* bq    = (const float*)d_in[4];
    const float* Wk    = (const float*)d_in[5];
    const float* bk    = (const float*)d_in[6];
    const float* Wv    = (const float*)d_in[7];
    const float* bv    = (const float*)d_in[8];
    const float* Wo    = (const float*)d_in[9];
    const float* bo    = (const float*)d_in[10];
    const float* gamma = (const float*)d_in[11];
    const float* beta  = (const float*)d_in[12];
    float* out = (float*)d_out;

    float *mu_p, *rs_p, *q_p, *k_p, *v_p, *c1_p, *c2_p;
    __nv_bfloat16 *xhq, *xlq, *xhk, *xlk, *xhv, *xlv, *wh_p, *wl_p, *aoh_p, *aol_p;
    cudaGetSymbolAddress((void**)&mu_p, g_mu);
    cudaGetSymbolAddress((void**)&rs_p, g_rs);
    cudaGetSymbolAddress((void**)&q_p,  g_q);
    cudaGetSymbolAddress((void**)&k_p,  g_k);
    cudaGetSymbolAddress((void**)&v_p,  g_v);
    cudaGetSymbolAddress((void**)&aoh_p, g_aoh);
    cudaGetSymbolAddress((void**)&aol_p, g_aol);
    cudaGetSymbolAddress((void**)&xhq, g_xh_q);
    cudaGetSymbolAddress((void**)&xlq, g_xl_q);
    cudaGetSymbolAddress((void**)&xhk, g_xh_k);
    cudaGetSymbolAddress((void**)&xlk, g_xl_k);
    cudaGetSymbolAddress((void**)&xhv, g_xh_v);
    cudaGetSymbolAddress((void**)&xlv, g_xl_v);
    cudaGetSymbolAddress((void**)&wh_p, g_wh);
    cudaGetSymbolAddress((void**)&wl_p, g_wl);
    cudaGetSymbolAddress((void**)&c1_p, g_c1);
    cudaGetSymbolAddress((void**)&c2_p, g_c2);

    // 1) LN stats + bf16 splits
    ln_split_kernel<<<3 * NROWS, 256>>>(Q, K, V);
    // 2) weight prep
    wprep_kernel<<<dim3(16, 16, 4), 256>>>(Wq, Wk, Wv, Wo, gamma);
    wcols_kernel<<<dim3(4, 3), 256>>>(Wq, Wk, Wv, gamma, beta, bq, bk, bv);

    // 3) projections via mma.sync bf16 3-pass
    size_t gsmem = NSTG * STG;   // 49152
    cudaFuncSetAttribute(gemm_mma_kernel<0>, cudaFuncAttributeMaxDynamicSharedMemorySize, (int)gsmem);
    cudaFuncSetAttribute(gemm_mma_kernel<1>, cudaFuncAttributeMaxDynamicSharedMemorySize, (int)gsmem);
    dim3 gg(Dm / BN, NROWS / BM);    // (8, 64)
    size_t WSZ = (size_t)Dm * Dm;
    gemm_mma_kernel<0><<<gg, 256, gsmem>>>(xhq, xlq, wh_p, wl_p,
                                           c1_p, c2_p, rs_p, mu_p, nullptr, q_p);
    gemm_mma_kernel<0><<<gg, 256, gsmem>>>(xhk, xlk, wh_p + WSZ, wl_p + WSZ,
                                           c1_p + Dm, c2_p + Dm, rs_p + NROWS, mu_p + NROWS,
                                           nullptr, k_p);
    gemm_mma_kernel<0><<<gg, 256, gsmem>>>(xhv, xlv, wh_p + 2 * WSZ, wl_p + 2 * WSZ,
                                           c1_p + 2 * Dm, c2_p + 2 * Dm,
                                           rs_p + 2 * NROWS, mu_p + 2 * NROWS,
                                           nullptr, v_p);

    // 4) attention (fp32), writes bf16-split row-major output
    size_t smem = 4 * 64 * APAD * sizeof(float);
    cudaFuncSetAttribute(attn_kernel, cudaFuncAttributeMaxDynamicSharedMemorySize, (int)smem);
    attn_kernel<<<dim3(Ss / 64, Bb * Hh), 256, smem>>>(aoh_p, aol_p);

    // 5) output projection + bias + residual
    gemm_mma_kernel<1><<<gg, 256, gsmem>>>(aoh_p, aol_p, wh_p + 3 * WSZ, wl_p + 3 * WSZ,
                                           nullptr, bo, nullptr, nullptr, Q, out);
}

// round 5
// speedup vs baseline: 2.0384x; 1.3951x over previous
#include <cuda_runtime.h>
#include <cuda_bf16.h>
#include <cstdint>
#include <math.h>

#define Dm 1024
#define Hh 16
#define DHd 64
#define Bb 4
#define Ss 2048
#define NROWS (Bb*Ss)   // 8192
#define LOG2E 1.4426950408889634f

// ---------------- static device scratch ----------------
__device__ float g_mu[3*NROWS];
__device__ float g_rs[3*NROWS];
__device__ __nv_bfloat16 g_xh_q[NROWS*Dm]; __device__ __nv_bfloat16 g_xl_q[NROWS*Dm];
__device__ __nv_bfloat16 g_xh_k[NROWS*Dm]; __device__ __nv_bfloat16 g_xl_k[NROWS*Dm];
__device__ __nv_bfloat16 g_xh_v[NROWS*Dm]; __device__ __nv_bfloat16 g_xl_v[NROWS*Dm];
__device__ __nv_bfloat16 g_wh[4*Dm*Dm];
__device__ __nv_bfloat16 g_wl[4*Dm*Dm];
__device__ float g_c1[3*Dm];
__device__ float g_c2[3*Dm];
// projections, bf16 hi/lo split
__device__ __nv_bfloat16 g_qh[NROWS*Dm], g_ql[NROWS*Dm];  // [bh][s][d], pre-scaled by LOG2E
__device__ __nv_bfloat16 g_kh[NROWS*Dm], g_kl[NROWS*Dm];  // [bh][s][d]
__device__ __nv_bfloat16 g_vh[NROWS*Dm], g_vl[NROWS*Dm];  // [bh][d][s]  (transposed)
__device__ __nv_bfloat16 g_aoh[NROWS*Dm], g_aol[NROWS*Dm]; // [b*s][D]

// ---------------- helpers ----------------
__device__ __forceinline__ uint32_t smem_u32(const void* p) {
    uint32_t a;
    asm("{ .reg .u64 t; cvta.to.shared.u64 t, %1; cvt.u32.u64 %0, t; }" : "=r"(a) : "l"(p));
    return a;
}
__device__ __forceinline__ void cp16(uint32_t s, const void* g) {
    asm volatile("cp.async.cg.shared.global [%0], [%1], 16;\n" :: "r"(s), "l"(g));
}
__device__ __forceinline__ void ldmA(uint32_t addr, uint32_t& r0, uint32_t& r1,
                                     uint32_t& r2, uint32_t& r3) {
    asm volatile("ldmatrix.sync.aligned.m8n8.x4.shared.b16 {%0,%1,%2,%3}, [%4];"
                 : "=r"(r0), "=r"(r1), "=r"(r2), "=r"(r3) : "r"(addr));
}
__device__ __forceinline__ void mma16816(float* c, uint32_t a0, uint32_t a1,
                                         uint32_t a2, uint32_t a3,
                                         uint32_t b0, uint32_t b1) {
    asm volatile("mma.sync.aligned.m16n8k16.row.col.f32.bf16.bf16.f32 "
                 "{%0,%1,%2,%3}, {%4,%5,%6,%7}, {%8,%9}, {%0,%1,%2,%3};"
                 : "+f"(c[0]), "+f"(c[1]), "+f"(c[2]), "+f"(c[3])
                 : "r"(a0), "r"(a1), "r"(a2), "r"(a3), "r"(b0), "r"(b1));
}
__device__ __forceinline__ float ex2f(float x) {
    float r; asm("ex2.approx.f32 %0, %1;" : "=f"(r) : "f"(x)); return r;
}
// 2^z via FFMA poly + exponent insert (no MUFU). z <= 0.
__device__ __forceinline__ float exp2poly(float z) {
    z = fmaxf(z, -126.f);
    float t = z + 12582912.f;                 // round-to-nearest integer
    int n = __float_as_int(t) - 0x4B400000;
    float f = z - (t - 12582912.f);           // f in [-0.5, 0.5]
    float p = fmaf(0.0096181291f, f, 0.055504109f);
    p = fmaf(p, f, 0.24022651f);
    p = fmaf(p, f, 0.69314718f);
    p = fmaf(p, f, 1.0f);
    return __int_as_float(__float_as_int(p) + (n << 23));
}
__device__ __forceinline__ uint32_t packbf2(float a, float b) {
    __nv_bfloat162 t;
    t.x = __float2bfloat16(a);
    t.y = __float2bfloat16(b);
    return *(uint32_t*)&t;
}

// ============================================================
// 1) LN stats + bf16 hi/lo split of raw inputs
// ============================================================
__global__ void ln_split_kernel(const float* __restrict__ Q,
                                const float* __restrict__ K,
                                const float* __restrict__ V) {
    int row = blockIdx.x;
    int which = row >> 13;
    int r = row & (NROWS - 1);
    const float* x; __nv_bfloat16* xh; __nv_bfloat16* xl;
    if (which == 0)      { x = Q; xh = g_xh_q; xl = g_xl_q; }
    else if (which == 1) { x = K; xh = g_xh_k; xl = g_xl_k; }
    else                 { x = V; xh = g_xh_v; xl = g_xl_v; }
    size_t base = (size_t)r * Dm;

    float v[4];
    float s = 0.f, s2 = 0.f;
    #pragma unroll
    for (int l = 0; l < 4; l++) {
        v[l] = x[base + threadIdx.x + l * 256];
        s += v[l]; s2 += v[l] * v[l];
    }
    #pragma unroll
    for (int o = 16; o > 0; o >>= 1) {
        s  += __shfl_xor_sync(0xffffffffu, s,  o);
        s2 += __shfl_xor_sync(0xffffffffu, s2, o);
    }
    __shared__ float sh[16];
    int w = threadIdx.x >> 5;
    if ((threadIdx.x & 31) == 0) { sh[w] = s; sh[w + 8] = s2; }
    __syncthreads();
    if (threadIdx.x == 0) {
        float ts = 0.f, ts2 = 0.f;
        #pragma unroll
        for (int i = 0; i < 8; i++) { ts += sh[i]; ts2 += sh[i + 8]; }
        float muv = ts / (float)Dm;
        float var = ts2 / (float)Dm - muv * muv;
        g_mu[row] = muv;
        g_rs[row] = rsqrtf(var + 1e-6f);
    }
    #pragma unroll
    for (int l = 0; l < 4; l++) {
        __nv_bfloat16 h = __float2bfloat16(v[l]);
        xh[base + threadIdx.x + l * 256] = h;
        xl[base + threadIdx.x + l * 256] = __float2bfloat16(v[l] - __bfloat162float(h));
    }
}

// ============================================================
// 2) weight prep (transpose, gamma-scale, bf16 split) + col constants
// ============================================================
__global__ void wprep_kernel(const float* __restrict__ Wq, const float* __restrict__ Wk,
                             const float* __restrict__ Wv, const float* __restrict__ Wo,
                             const float* __restrict__ gamma) {
    int w = blockIdx.z;
    const float* W = (w == 0) ? Wq : (w == 1) ? Wk : (w == 2) ? Wv : Wo;
    __shared__ float ts[64][65];
    int n0 = blockIdx.x * 64, k0 = blockIdx.y * 64;
    int tx = threadIdx.x & 63, ty = threadIdx.x >> 6;
    #pragma unroll
    for (int l = 0; l < 16; l++) {
        int k = ty + l * 4;
        float g = (w < 3) ? gamma[k0 + k] : 1.f;
        ts[k][tx] = g * W[(size_t)(k0 + k) * Dm + n0 + tx];
    }
    __syncthreads();
    __nv_bfloat16* whp = g_wh + (size_t)w * Dm * Dm;
    __nv_bfloat16* wlp = g_wl + (size_t)w * Dm * Dm;
    #pragma unroll
    for (int l = 0; l < 16; l++) {
        int n = ty + l * 4;
        float val = ts[tx][n];
        __nv_bfloat16 h = __float2bfloat16(val);
        size_t o = (size_t)(n0 + n) * Dm + k0 + tx;
        whp[o] = h;
        wlp[o] = __float2bfloat16(val - __bfloat162float(h));
    }
}

__global__ void wcols_kernel(const float* __restrict__ Wq, const float* __restrict__ Wk,
                             const float* __restrict__ Wv,
                             const float* __restrict__ gamma, const float* __restrict__ beta,
                             const float* __restrict__ bq, const float* __restrict__ bk,
                             const float* __restrict__ bv) {
    int w = blockIdx.y;
    int n = blockIdx.x * 256 + threadIdx.x;
    const float* W = (w == 0) ? Wq : (w == 1) ? Wk : Wv;
    const float* b = (w == 0) ? bq : (w == 1) ? bk : bv;
    float a1 = 0.f, a2 = 0.f;
    for (int k = 0; k < Dm; k++) {
        float wv = W[(size_t)k * Dm + n];
        a1 += gamma[k] * wv;
        a2 += beta[k] * wv;
    }
    g_c1[w * Dm + n] = a1;
    g_c2[w * Dm + n] = a2 + b[n];
}

// ============================================================
// 3) bf16 mma GEMM, 3-pass split.
//    MODE 0: Q  -> LN epi, *LOG2E, bf16 split [bh][s][d]
//    MODE 3: K  -> LN epi, bf16 split [bh][s][d]
//    MODE 2: V  -> LN epi, bf16 split transposed [bh][d][s]
//    MODE 1: O  -> fp32 +bias +residual row-major
// ============================================================
#define BM 128
#define BN 128
#define BK 32
#define KBYTES 64
#define STG_A 8192
#define STG   16384
#define NSTG  3
#define NT    96

template<int MODE>
__global__ void __launch_bounds__(256, 1) gemm_mma_kernel(
    const __nv_bfloat16* __restrict__ Ah, const __nv_bfloat16* __restrict__ Al,
    const __nv_bfloat16* __restrict__ Bh, const __nv_bfloat16* __restrict__ Bl,
    const float* __restrict__ c1, const float* __restrict__ c2,
    const float* __restrict__ rs, const float* __restrict__ mu,
    const float* __restrict__ resid,
    float* __restrict__ outF,
    __nv_bfloat16* __restrict__ outH, __nv_bfloat16* __restrict__ outL)
{
    extern __shared__ char smem[];
    uint32_t sbase = smem_u32(smem);
    int tid = threadIdx.x, lane = tid & 31, wid = tid >> 5;
    int warpM = wid & 1, warpN = wid >> 1;
    int m0 = blockIdx.y * BM, n0 = blockIdx.x * BN;

    float acc[4][4][4] = {};

    auto prefetch = [&](int t) {
        int s = t % NSTG;
        int pass = t >> 5, kb = (t & 31) * BK;
        const __nv_bfloat16* Ap = (pass == 2) ? Al : Ah;
        const __nv_bfloat16* Bp = (pass == 1) ? Bl : Bh;
        uint32_t sa = sbase + s * STG, sb = sa + STG_A;
        #pragma unroll
        for (int l = 0; l < 2; l++) {
            int e = tid + l * 256;
            int m = e >> 2, kc = e & 3;
            uint32_t sw = m * KBYTES + ((kc ^ (m & 3)) << 4);
            cp16(sa + sw, Ap + (size_t)(m0 + m) * Dm + kb + kc * 8);
            cp16(sb + sw, Bp + (size_t)(n0 + m) * Dm + kb + kc * 8);
        }
    };

    prefetch(0); asm volatile("cp.async.commit_group;\n" ::: "memory");
    prefetch(1); asm volatile("cp.async.commit_group;\n" ::: "memory");

    for (int t = 0; t < NT; t++) {
        asm volatile("cp.async.wait_group 1;\n" ::: "memory");
        __syncthreads();
        int s = t % NSTG;
        uint32_t sa = sbase + s * STG, sb = sa + STG_A;
        #pragma unroll
        for (int ks = 0; ks < 2; ks++) {
            uint32_t afr[4][4];
            #pragma unroll
            for (int mf = 0; mf < 4; mf++) {
                int row = warpM * 64 + mf * 16 + (lane & 15);
                int chunk = ks * 2 + (lane >> 4);
                uint32_t addr = sa + row * KBYTES + ((chunk ^ (row & 3)) << 4);
                ldmA(addr, afr[mf][0], afr[mf][1], afr[mf][2], afr[mf][3]);
            }
            #pragma unroll
            for (int nf = 0; nf < 4; nf++) {
                int n = warpN * 32 + nf * 8 + (lane >> 2);
                int kb0 = ks * 32 + (lane & 3) * 4;
                int c0 = kb0 >> 4, o0 = kb0 & 15;
                uint32_t ab0 = sb + n * KBYTES + (((c0 ^ (n & 3)) << 4) | o0);
                uint32_t ab1 = sb + n * KBYTES + ((((c0 + 1) ^ (n & 3)) << 4) | o0);
                uint32_t b0, b1;
                asm volatile("ld.shared.b32 %0, [%1];" : "=r"(b0) : "r"(ab0));
                asm volatile("ld.shared.b32 %0, [%1];" : "=r"(b1) : "r"(ab1));
                #pragma unroll
                for (int mf = 0; mf < 4; mf++)
                    mma16816(acc[mf][nf], afr[mf][0], afr[mf][1], afr[mf][2], afr[mf][3],
                             b0, b1);
            }
        }
        __syncthreads();
        if (t + 2 < NT) prefetch(t + 2);
        asm volatile("cp.async.commit_group;\n" ::: "memory");
    }

    int groupID = lane >> 2, tg = lane & 3;
    #pragma unroll
    for (int mf = 0; mf < 4; mf++) {
        #pragma unroll
        for (int half = 0; half < 2; half++) {
            int r = m0 + warpM * 64 + mf * 16 + groupID + half * 8;
            float rsv = 1.f, muv = 0.f;
            if (MODE != 1) { rsv = rs[r]; muv = mu[r]; }
            int b = r >> 11, srow = r & 2047;
            #pragma unroll
            for (int nf = 0; nf < 4; nf++) {
                int c = n0 + warpN * 32 + nf * 8 + 2 * tg;
                float x0 = acc[mf][nf][2 * half + 0];
                float x1 = acc[mf][nf][2 * half + 1];
                if (MODE == 1) {
                    float2 bo2 = *(const float2*)(c2 + c);
                    float2 q2  = *(const float2*)(resid + (size_t)r * Dm + c);
                    float2 o;
                    o.x = x0 + bo2.x + q2.x;
                    o.y = x1 + bo2.y + q2.y;
                    *(float2*)(outF + (size_t)r * Dm + c) = o;
                } else {
                    float2 c1v = *(const float2*)(c1 + c);
                    float2 c2v = *(const float2*)(c2 + c);
                    float o0 = rsv * (x0 - muv * c1v.x) + c2v.x;
                    float o1 = rsv * (x1 - muv * c1v.y) + c2v.y;
                    if (MODE == 0) { o0 *= LOG2E; o1 *= LOG2E; }
                    __nv_bfloat16 h0 = __float2bfloat16(o0);
                    __nv_bfloat16 h1 = __float2bfloat16(o1);
                    float l0 = o0 - __bfloat162float(h0);
                    float l1 = o1 - __bfloat162float(h1);
                    int hd = c >> 6, dd = c & 63;
                    int bh = b * Hh + hd;
                    if (MODE == 2) {
                        size_t a0 = ((size_t)(bh * DHd + dd)) * Ss + srow;
                        size_t a1 = ((size_t)(bh * DHd + dd + 1)) * Ss + srow;
                        outH[a0] = h0; outH[a1] = h1;
                        outL[a0] = __float2bfloat16(l0);
                        outL[a1] = __float2bfloat16(l1);
                    } else {
                        size_t ad = ((size_t)(bh * Ss + srow)) * DHd + dd;
                        __nv_bfloat162 hp; hp.x = h0; hp.y = h1;
                        *(uint32_t*)(outH + ad) = *(uint32_t*)&hp;
                        *(uint32_t*)(outL + ad) = packbf2(l0, l1);
                    }
                }
            }
        }
    }
}

// ============================================================
// 4) tensor-core causal attention, log2-domain softmax (no MUFU exp)
//    block: 256 thr (8 warps x 16 rows), q-tile 128, k-tile 64
// ============================================================
__device__ __forceinline__ void loadKV(int bh, int t, uint32_t base, int tid) {
    int kt = t * 64;
    const __nv_bfloat16* khp = g_kh + ((size_t)bh * Ss + kt) * DHd;
    const __nv_bfloat16* klp = g_kl + ((size_t)bh * Ss + kt) * DHd;
    const __nv_bfloat16* vhp = g_vh + (size_t)bh * DHd * Ss + kt;
    const __nv_bfloat16* vlp = g_vl + (size_t)bh * DHd * Ss + kt;
    #pragma unroll
    for (int l = 0; l < 2; l++) {
        int e = tid + l * 256;
        int row = e >> 3, c = e & 7;
        uint32_t d = row * 128 + ((c ^ (row & 7)) << 4);
        cp16(base + d,         khp + (size_t)row * DHd + c * 8);
        cp16(base + 8192 + d,  klp + (size_t)row * DHd + c * 8);
        cp16(base + 16384 + d, vhp + (size_t)row * Ss + c * 8);
        cp16(base + 24576 + d, vlp + (size_t)row * Ss + c * 8);
    }
}

__global__ void __launch_bounds__(256, 1) attn_mma_kernel() {
    extern __shared__ char smraw[];
    uint32_t sb = smem_u32(smraw);
    const uint32_t QHs = sb;                 // 16K
    const uint32_t KVs = sb + 32768;         // 2 x 32K buffers
    int tid = threadIdx.x, lane = tid & 31, wid = tid >> 5;
    int groupID = lane >> 2, tg = lane & 3;
    int bh = blockIdx.y;
    int mt = (int)(gridDim.x - 1) - (int)blockIdx.x;   // big tiles first
    int q0 = mt * 128;
    int numt = 2 * mt + 2;

    const __nv_bfloat16* qhp = g_qh + ((size_t)bh * Ss + q0) * DHd;
    const __nv_bfloat16* qlp = g_ql + ((size_t)bh * Ss + q0) * DHd;

    #pragma unroll
    for (int l = 0; l < 4; l++) {
        int e = tid + l * 256;
        int row = e >> 3, c = e & 7;
        uint32_t d = row * 128 + ((c ^ (row & 7)) << 4);
        cp16(QHs + d,         qhp + (size_t)row * DHd + c * 8);
        cp16(QHs + 16384 + d, qlp + (size_t)row * DHd + c * 8);
    }
    asm volatile("cp.async.commit_group;\n" ::: "memory");
    loadKV(bh, 0, KVs, tid);
    asm volatile("cp.async.commit_group;\n" ::: "memory");
    asm volatile("cp.async.wait_group 1;\n" ::: "memory");
    __syncthreads();

    uint32_t qh[4][4], ql[4][4];
    #pragma unroll
    for (int kf = 0; kf < 4; kf++) {
        int row = wid * 16 + (lane & 15);
        int ch = 2 * kf + (lane >> 4);
        uint32_t ad = QHs + row * 128 + ((ch ^ (row & 7)) << 4);
        ldmA(ad, qh[kf][0], qh[kf][1], qh[kf][2], qh[kf][3]);
        ldmA(ad + 16384, ql[kf][0], ql[kf][1], ql[kf][2], ql[kf][3]);
    }

    float m[2] = {-1e30f, -1e30f}, lsum[2] = {0.f, 0.f};
    float oacc[8][4] = {};

    for (int t = 0; t < numt; t++) {
        if (t + 1 < numt) loadKV(bh, t + 1, KVs + ((t + 1) & 1) * 32768, tid);
        asm volatile("cp.async.commit_group;\n" ::: "memory");
        asm volatile("cp.async.wait_group 1;\n" ::: "memory");
        __syncthreads();
        uint32_t KB = KVs + (t & 1) * 32768;

        float sacc[8][4] = {};
        #pragma unroll
        for (int pass = 0; pass < 3; pass++) {
            uint32_t Bbase = (pass == 1) ? (KB + 8192) : KB;
            uint32_t (*Af)[4] = (pass == 2) ? ql : qh;
            #pragma unroll
            for (int kf = 0; kf < 4; kf++) {
                #pragma unroll
                for (int nf2 = 0; nf2 < 4; nf2++) {
                    int row = nf2 * 16 + (lane & 15);
                    int ch = 2 * kf + (lane >> 4);
                    uint32_t ad = Bbase + row * 128 + ((ch ^ (row & 7)) << 4);
                    uint32_t r0, r1, r2, r3;
                    ldmA(ad, r0, r1, r2, r3);
                    mma16816(sacc[2 * nf2],     Af[kf][0], Af[kf][1], Af[kf][2], Af[kf][3], r0, r2);
                    mma16816(sacc[2 * nf2 + 1], Af[kf][0], Af[kf][1], Af[kf][2], Af[kf][3], r1, r3);
                }
            }
        }

        if (t >= numt - 2) {
            int kt = t * 64;
            int qrow = q0 + wid * 16 + groupID;
            #pragma unroll
            for (int nf = 0; nf < 8; nf++) {
                int k0 = kt + nf * 8 + 2 * tg;
                if (k0     > qrow)     sacc[nf][0] = -1e30f;
                if (k0 + 1 > qrow)     sacc[nf][1] = -1e30f;
                if (k0     > qrow + 8) sacc[nf][2] = -1e30f;
                if (k0 + 1 > qrow + 8) sacc[nf][3] = -1e30f;
            }
        }

        float alpha[2];
        #pragma unroll
        for (int h = 0; h < 2; h++) {
            float rm = -1e30f;
            #pragma unroll
            for (int nf = 0; nf < 8; nf++)
                rm = fmaxf(rm, fmaxf(sacc[nf][2 * h], sacc[nf][2 * h + 1]));
            rm = fmaxf(rm, __shfl_xor_sync(0xffffffffu, rm, 1));
            rm = fmaxf(rm, __shfl_xor_sync(0xffffffffu, rm, 2));
            float mn = fmaxf(m[h], rm);
            alpha[h] = ex2f(m[h] - mn);
            m[h] = mn;
            float ls = 0.f;
            #pragma unroll
            for (int nf = 0; nf < 8; nf++) {
                float p0 = exp2poly(sacc[nf][2 * h]     - mn);
                float p1 = exp2poly(sacc[nf][2 * h + 1] - mn);
                sacc[nf][2 * h] = p0; sacc[nf][2 * h + 1] = p1;
                ls += p0 + p1;
            }
            lsum[h] = lsum[h] * alpha[h] + ls;
        }
        #pragma unroll
        for (int nd = 0; nd < 8; nd++) {
            oacc[nd][0] *= alpha[0]; oacc[nd][1] *= alpha[0];
            oacc[nd][2] *= alpha[1]; oacc[nd][3] *= alpha[1];
        }

        uint32_t pah[4][4], pal[4][4];
        #pragma unroll
        for (int kf = 0; kf < 4; kf++) {
            #pragma unroll
            for (int q = 0; q < 4; q++) {
                int nf = 2 * kf + (q >> 1);
                float x0 = sacc[nf][(q & 1) * 2], x1 = sacc[nf][(q & 1) * 2 + 1];
                __nv_bfloat16 h0 = __float2bfloat16(x0), h1 = __float2bfloat16(x1);
                __nv_bfloat162 hp; hp.x = h0; hp.y = h1;
                pah[kf][q] = *(uint32_t*)&hp;
                pal[kf][q] = packbf2(x0 - __bfloat162float(h0), x1 - __bfloat162float(h1));
            }
        }

        #pragma unroll
        for (int pass = 0; pass < 3; pass++) {
            uint32_t Vbase = (pass == 1) ? (KB + 24576) : (KB + 16384);
            uint32_t (*Pf)[4] = (pass == 2) ? pal : pah;
            #pragma unroll
            for (int kf = 0; kf < 4; kf++) {
                #pragma unroll
                for (int nd2 = 0; nd2 < 4; nd2++) {
                    int row = nd2 * 16 + (lane & 15);
                    int ch = 2 * kf + (lane >> 4);
                    uint32_t ad = Vbase + row * 128 + ((ch ^ (row & 7)) << 4);
                    uint32_t r0, r1, r2, r3;
                    ldmA(ad, r0, r1, r2, r3);
                    mma16816(oacc[2 * nd2],     Pf[kf][0], Pf[kf][1], Pf[kf][2], Pf[kf][3], r0, r2);
                    mma16816(oacc[2 * nd2 + 1], Pf[kf][0], Pf[kf][1], Pf[kf][2], Pf[kf][3], r1, r3);
                }
            }
        }
        __syncthreads();
    }

    #pragma unroll
    for (int h = 0; h < 2; h++) {
        lsum[h] += __shfl_xor_sync(0xffffffffu, lsum[h], 1);
        lsum[h] += __shfl_xor_sync(0xffffffffu, lsum[h], 2);
    }
    int b = bh >> 4, hd = bh & 15;
    #pragma unroll
    for (int h = 0; h < 2; h++) {
        int q = q0 + wid * 16 + groupID + 8 * h;
        float inv = 1.f / lsum[h];
        size_t rowbase = ((size_t)(b * Ss + q)) * Dm + hd * 64;
        #pragma unroll
        for (int nd = 0; nd < 8; nd++) {
            float x0 = oacc[nd][2 * h] * inv, x1 = oacc[nd][2 * h + 1] * inv;
            __nv_bfloat16 h0 = __float2bfloat16(x0), h1 = __float2bfloat16(x1);
            __nv_bfloat162 hp; hp.x = h0; hp.y = h1;
            size_t ad = rowbase + nd * 8 + 2 * tg;
            *(uint32_t*)(g_aoh + ad) = *(uint32_t*)&hp;
            *(uint32_t*)(g_aol + ad) = packbf2(x0 - __bfloat162float(h0),
                                               x1 - __bfloat162float(h1));
        }
    }
}

// ============================================================
// launch
// ============================================================
extern "C" void kernel_launch(void* const* d_in, const int* in_sizes, int n_in,
                              void* d_out, int out_size) {
    const float* Q     = (const float*)d_in[0];
    const float* K     = (const float*)d_in[1];
    const float* V     = (const float*)d_in[2];
    const float* Wq    = (const float*)d_in[3];
    const float* bq    = (const float*)d_in[4];
    const float* Wk    = (const float*)d_in[5];
    const float* bk    = (const float*)d_in[6];
    const float* Wv    = (const float*)d_in[7];
    const float* bv    = (const float*)d_in[8];
    const float* Wo    = (const float*)d_in[9];
    const float* bo    = (const float*)d_in[10];
    const float* gamma = (const float*)d_in[11];
    const float* beta  = (const float*)d_in[12];
    float* out = (float*)d_out;

    float *mu_p, *rs_p, *c1_p, *c2_p;
    __nv_bfloat16 *xhq, *xlq, *xhk, *xlk, *xhv, *xlv, *wh_p, *wl_p;
    __nv_bfloat16 *qh_p, *ql_p, *kh_p, *kl_p, *vh_p, *vl_p, *aoh_p, *aol_p;
    cudaGetSymbolAddress((void**)&mu_p, g_mu);
    cudaGetSymbolAddress((void**)&rs_p, g_rs);
    cudaGetSymbolAddress((void**)&c1_p, g_c1);
    cudaGetSymbolAddress((void**)&c2_p, g_c2);
    cudaGetSymbolAddress((void**)&xhq, g_xh_q);
    cudaGetSymbolAddress((void**)&xlq, g_xl_q);
    cudaGetSymbolAddress((void**)&xhk, g_xh_k);
    cudaGetSymbolAddress((void**)&xlk, g_xl_k);
    cudaGetSymbolAddress((void**)&xhv, g_xh_v);
    cudaGetSymbolAddress((void**)&xlv, g_xl_v);
    cudaGetSymbolAddress((void**)&wh_p, g_wh);
    cudaGetSymbolAddress((void**)&wl_p, g_wl);
    cudaGetSymbolAddress((void**)&qh_p, g_qh);
    cudaGetSymbolAddress((void**)&ql_p, g_ql);
    cudaGetSymbolAddress((void**)&kh_p, g_kh);
    cudaGetSymbolAddress((void**)&kl_p, g_kl);
    cudaGetSymbolAddress((void**)&vh_p, g_vh);
    cudaGetSymbolAddress((void**)&vl_p, g_vl);
    cudaGetSymbolAddress((void**)&aoh_p, g_aoh);
    cudaGetSymbolAddress((void**)&aol_p, g_aol);

    ln_split_kernel<<<3 * NROWS, 256>>>(Q, K, V);
    wprep_kernel<<<dim3(16, 16, 4), 256>>>(Wq, Wk, Wv, Wo, gamma);
    wcols_kernel<<<dim3(4, 3), 256>>>(Wq, Wk, Wv, gamma, beta, bq, bk, bv);

    size_t gsmem = NSTG * STG;
    cudaFuncSetAttribute(gemm_mma_kernel<0>, cudaFuncAttributeMaxDynamicSharedMemorySize, (int)gsmem);
    cudaFuncSetAttribute(gemm_mma_kernel<1>, cudaFuncAttributeMaxDynamicSharedMemorySize, (int)gsmem);
    cudaFuncSetAttribute(gemm_mma_kernel<2>, cudaFuncAttributeMaxDynamicSharedMemorySize, (int)gsmem);
    cudaFuncSetAttribute(gemm_mma_kernel<3>, cudaFuncAttributeMaxDynamicSharedMemorySize, (int)gsmem);
    dim3 gg(Dm / BN, NROWS / BM);
    size_t WSZ = (size_t)Dm * Dm;

    gemm_mma_kernel<0><<<gg, 256, gsmem>>>(xhq, xlq, wh_p, wl_p,
                                           c1_p, c2_p, rs_p, mu_p, nullptr,
                                           nullptr, qh_p, ql_p);
    gemm_mma_kernel<3><<<gg, 256, gsmem>>>(xhk, xlk, wh_p + WSZ, wl_p + WSZ,
                                           c1_p + Dm, c2_p + Dm, rs_p + NROWS, mu_p + NROWS,
                                           nullptr, nullptr, kh_p, kl_p);
    gemm_mma_kernel<2><<<gg, 256, gsmem>>>(xhv, xlv, wh_p + 2 * WSZ, wl_p + 2 * WSZ,
                                           c1_p + 2 * Dm, c2_p + 2 * Dm,
                                           rs_p + 2 * NROWS, mu_p + 2 * NROWS,
                                           nullptr, nullptr, vh_p, vl_p);

    size_t asmem = 98304;   // 32K Q + 2x32K KV
    cudaFuncSetAttribute(attn_mma_kernel, cudaFuncAttributeMaxDynamicSharedMemorySize, (int)asmem);
    attn_mma_kernel<<<dim3(16, 64), 256, asmem>>>();

    gemm_mma_kernel<1><<<gg, 256, gsmem>>>(aoh_p, aol_p, wh_p + 3 * WSZ, wl_p + 3 * WSZ,
                                           nullptr, bo, nullptr, nullptr, Q,
                                           out, nullptr, nullptr);
}